// round 2
// baseline (speedup 1.0000x reference)
#include <cuda_runtime.h>

// filtfilt (order-2 IIR, 3-tap b/a) over 1024 rows x 32768 samples.
//
// Key facts exploited:
//  - The per-row max-abs normalization in the reference cancels exactly
//    (everything is linear, zero initial state) -> skipped.
//  - Filter poles have |lambda| = sqrt(1/3) ~= 0.577, so state memory is
//    ~50 samples. Each row is chopped into independent chunks of CL=128
//    samples; each thread runs a WARM=48 step zero-state warm-up before its
//    chunk. Initial-state error after warm-up: 0.577^48 ~ 3.5e-11 (relative),
//    vastly below the 1e-3 tolerance.
//
// Kernel 1: forward lfilter on odd-extended x -> scratch y1 (device global).
// Kernel 2: backward lfilter on reversed y1 -> cropped output.

#define N      32768
#define PAD    9
#define NE     (N + 2 * PAD)          // 32786
#define ROWS   1024
#define CL     128                    // chunk length (outputs per thread)
#define WARM   48                     // zero-state warm-up steps
#define NCHUNK ((NE + CL - 1) / CL)   // 257
#define Y1_STRIDE 32800               // 128B-aligned row stride for scratch

// 1024 * 32800 * 4B = ~134 MB static scratch (allowed: not an allocation
// inside kernel_launch; lives in the module image).
__device__ float g_y1[(size_t)ROWS * Y1_STRIDE];

struct Coef { float b0, b1, b2, na1, na2; };

__device__ __forceinline__ Coef load_coef(const float* __restrict__ b,
                                          const float* __restrict__ a) {
    Coef c;
    float ia0 = 1.0f / a[0];
    c.b0  = b[0] * ia0;
    c.b1  = b[1] * ia0;
    c.b2  = b[2] * ia0;
    c.na1 = -(a[1] * ia0);
    c.na2 = -(a[2] * ia0);
    return c;
}

// Odd-extended signal: xe[t], t in [0, NE).
//   t <  PAD      : 2*x[0]   - x[PAD - t]
//   PAD..N+PAD-1  : x[t - PAD]
//   t >= N+PAD    : 2*x[N-1] - x[2N-2-(t-PAD)]
__device__ __forceinline__ float load_xe(const float* __restrict__ xr, int t) {
    int i = t - PAD;
    if (i < 0)  return 2.0f * xr[0]     - xr[-i];
    if (i >= N) return 2.0f * xr[N - 1] - xr[2 * N - 2 - i];
    return __ldg(xr + i);
}

__device__ __forceinline__ void step(const Coef& c, float xv,
                                     float& z0, float& z1, float& y) {
    y  = fmaf(c.b0, xv, z0);                       // y = b0*x + z0
    z0 = fmaf(c.na1, y, fmaf(c.b1, xv, z1));       // z0' = z1 + b1*x - a1*y
    z1 = fmaf(c.na2, y, c.b2 * xv);                // z1' = b2*x - a2*y
}

__global__ void fwd_kernel(const float* __restrict__ x,
                           const float* __restrict__ b,
                           const float* __restrict__ a) {
    int chunk = blockIdx.x * blockDim.x + threadIdx.x;
    if (chunk >= NCHUNK) return;
    int row = blockIdx.y;

    const float* xr = x + (size_t)row * N;
    float*       yr = g_y1 + (size_t)row * Y1_STRIDE;
    Coef c = load_coef(b, a);

    int s  = chunk * CL;
    int e  = min(s + CL, NE);
    int ws = max(0, s - WARM);

    float z0 = 0.0f, z1 = 0.0f, y;
    for (int t = ws; t < s; ++t) {                 // warm-up (discard)
        step(c, load_xe(xr, t), z0, z1, y);
    }
    for (int t = s; t < e; ++t) {                  // real chunk
        step(c, load_xe(xr, t), z0, z1, y);
        yr[t] = y;
    }
}

__global__ void bwd_kernel(const float* __restrict__ b,
                           const float* __restrict__ a,
                           float* __restrict__ out) {
    int chunk = blockIdx.x * blockDim.x + threadIdx.x;
    if (chunk >= NCHUNK) return;
    int row = blockIdx.y;

    const float* yr   = g_y1 + (size_t)row * Y1_STRIDE;
    float*       outr = out + (size_t)row * N;
    Coef c = load_coef(b, a);

    int s = chunk * CL;                            // this thread's output span [s, e)
    int e = min(s + CL, NE);
    int wstart = min(NE - 1, e - 1 + WARM);

    float z0 = 0.0f, z1 = 0.0f, y;
    for (int u = wstart; u >= e; --u) {            // warm-up (descending)
        step(c, yr[u], z0, z1, y);
    }
    for (int u = e - 1; u >= s; --u) {             // real chunk
        step(c, yr[u], z0, z1, y);
        if (u >= PAD && u < NE - PAD)              // crop pad, reverse is implicit
            outr[u - PAD] = y;
    }
}

extern "C" void kernel_launch(void* const* d_in, const int* in_sizes, int n_in,
                              void* d_out, int out_size) {
    const float* x = (const float*)d_in[0];
    const float* b = (const float*)d_in[1];
    const float* a = (const float*)d_in[2];
    float* out = (float*)d_out;

    dim3 block(128);
    dim3 grid((NCHUNK + 127) / 128, ROWS);
    fwd_kernel<<<grid, block>>>(x, b, a);
    bwd_kernel<<<grid, block>>>(b, a, out);
}

// round 3
// speedup vs baseline: 1.9253x; 1.9253x over previous
#include <cuda_runtime.h>

// Fused filtfilt (order-2 IIR) over 1024 rows x 32768 fp32 samples.
//
// - Normalization in the reference cancels exactly (linear, zero init state).
// - Poles |lambda| = 0.577 -> 48-step warm-up gives ~3.6e-12 state error, so
//   rows split into independent per-thread chunks of CL=129.
// - ONE kernel: tile staged in SMEM. Coalesced load of odd-extended x,
//   forward filter in-place in SMEM (plus 48-sample tail), backward filter
//   in-place in SMEM, coalesced store. No global scratch at all.
//
// Phase discipline for in-place updates: every phase that READS another
// thread's region keeps its state in registers and is separated from the
// phase that WRITES that region by __syncthreads().

#define N        32768
#define PAD      9
#define NE       (N + 2 * PAD)        // 32786
#define ROWS     1024
#define WARM     48
#define THREADS  128
#define CL       129                  // chunk per thread
#define TILE     (CL * THREADS)       // 16512 -> 2 tiles per row
#define NTILE    2
#define SMEM_RAW (TILE + 2 * WARM)    // 16608 floats
#define SMEM_PADDED (SMEM_RAW + (SMEM_RAW >> 5))  // +1 float per 32 (banks)
#define SMEM_BYTES (SMEM_PADDED * 4)

__device__ __forceinline__ int pidx(int L) { return L + (L >> 5); }

__device__ __forceinline__ void step(float b0, float b1, float b2,
                                     float na1, float na2, float xv,
                                     float& z0, float& z1, float& y) {
    y  = fmaf(b0, xv, z0);                       // y   = b0*x + z0
    z0 = fmaf(na1, y, fmaf(b1, xv, z1));         // z0' = z1 + b1*x - a1*y
    z1 = fmaf(na2, y, b2 * xv);                  // z1' = b2*x - a2*y
}

__global__ __launch_bounds__(THREADS)
void filtfilt_kernel(const float* __restrict__ x,
                     const float* __restrict__ bc,
                     const float* __restrict__ ac,
                     float* __restrict__ out) {
    extern __shared__ float sm[];

    const int row  = blockIdx.y;
    const int base = blockIdx.x * TILE;          // tile start in ext domain
    const int tlen = min(TILE, NE - base);       // samples this tile owns

    const float* xr   = x   + (size_t)row * N;
    float*       outr = out + (size_t)row * N;

    const float ia0 = 1.0f / ac[0];
    const float b0  = bc[0] * ia0;
    const float b1  = bc[1] * ia0;
    const float b2  = bc[2] * ia0;
    const float na1 = -(ac[1] * ia0);
    const float na2 = -(ac[2] * ia0);

    // ---- Phase 0: coalesced load of odd-extended x into SMEM ----
    // SMEM local coordinate L covers ext positions [base-WARM, base+tlen+WARM)
    const int len = tlen + 2 * WARM;
    for (int idx = threadIdx.x; idx < len; idx += THREADS) {
        int p = base - WARM + idx;               // ext-domain position
        float v = 0.0f;
        if (p >= 0 && p < NE) {
            int i = p - PAD;
            if (i < 0)       v = 2.0f * xr[0]     - xr[-i];
            else if (i >= N) v = 2.0f * xr[N - 1] - xr[2 * N - 2 - i];
            else             v = xr[i];
        }
        sm[pidx(idx)] = v;
    }
    __syncthreads();

    const int s = threadIdx.x * CL;              // chunk start, rel. to base
    const bool active = (s < tlen);
    const int e = active ? min(s + CL, tlen) : s;

    // ---- Phase F1: forward warm-up (reads x, state in regs) ----
    float z0 = 0.0f, z1 = 0.0f, y;
    if (active) {
        int ws = max(0, base + s - WARM) - base; // rel. warm-up start
        for (int t = ws; t < s; ++t) {
            step(b0, b1, b2, na1, na2, sm[pidx(t + WARM)], z0, z1, y);
        }
    }
    __syncthreads();

    // ---- Phase F2: forward body, in-place x -> y1 (+ tail by last chunk) ----
    if (active) {
        int ebody = e;
        if (e == tlen)                            // unique last active chunk
            ebody = min(e + WARM, NE - base);     // extra tail for bwd warm-up
        for (int t = s; t < ebody; ++t) {
            int L = pidx(t + WARM);
            step(b0, b1, b2, na1, na2, sm[L], z0, z1, y);
            sm[L] = y;
        }
    }
    __syncthreads();

    // ---- Phase B1: backward warm-up (reads y1 from neighbor, regs only) ----
    z0 = 0.0f; z1 = 0.0f;
    if (active) {
        int u0 = min(e - 1 + WARM, NE - base - 1); // clamp = exact at seq end
        for (int u = u0; u >= e; --u) {
            step(b0, b1, b2, na1, na2, sm[pidx(u + WARM)], z0, z1, y);
        }
    }
    __syncthreads();

    // ---- Phase B2: backward body, in-place y1 -> y2 ----
    if (active) {
        for (int u = e - 1; u >= s; --u) {
            int L = pidx(u + WARM);
            step(b0, b1, b2, na1, na2, sm[L], z0, z1, y);
            sm[L] = y;
        }
    }
    __syncthreads();

    // ---- Phase 5: coalesced store (crop PAD; reversal is implicit) ----
    for (int idx = threadIdx.x; idx < tlen; idx += THREADS) {
        int g = base + idx;
        if (g >= PAD && g < NE - PAD)
            outr[g - PAD] = sm[pidx(idx + WARM)];
    }
}

extern "C" void kernel_launch(void* const* d_in, const int* in_sizes, int n_in,
                              void* d_out, int out_size) {
    const float* x = (const float*)d_in[0];
    const float* b = (const float*)d_in[1];
    const float* a = (const float*)d_in[2];
    float* out = (float*)d_out;

    cudaFuncSetAttribute(filtfilt_kernel,
                         cudaFuncAttributeMaxDynamicSharedMemorySize,
                         SMEM_BYTES);

    dim3 grid(NTILE, ROWS);
    filtfilt_kernel<<<grid, THREADS, SMEM_BYTES>>>(x, b, a, out);
}

// round 4
// speedup vs baseline: 2.6760x; 1.3899x over previous
#include <cuda_runtime.h>

// Fused filtfilt (order-2 IIR) over 1024 rows x 32768 fp32 samples.
//
// - Normalization in the reference cancels exactly (linear, zero init state).
// - Poles |lambda|=0.577 -> 48-step warm-up ~3.6e-12 state error; rows split
//   into independent per-thread chunks.
// - State-space unroll-by-4:  s_{t+4} = A^4 s_t + sum_j A^{3-j} g x_{t+j}.
//   Critical path: 2 dependent FMAs per 4 samples (4x shorter than scalar).
//   Outputs y_{t+j} = (impulse-response conv of x) + (row of A^j) . s_t, all
//   off the critical path. Warm-up groups skip y entirely (state only).
// - CL=97 (odd -> conflict-free LDS at per-thread stride), 50KB smem ->
//   4 blocks/SM, 16 warps/SM.

#define N        32768
#define PAD      9
#define NE       (N + 2 * PAD)        // 32786
#define ROWS     1024
#define WARM     48
#define THREADS  128
#define CL       97                   // odd: conflict-free per-thread stride
#define TILE     (CL * THREADS)       // 12416
#define NTILE    3                    // 3*12416 = 37248 >= NE
#define SMEM_FLOATS (TILE + 2 * WARM) // 12512
#define SMEM_BYTES  (SMEM_FLOATS * 4) // 50048

struct C {
    float b0, na1, na2;
    float g3x, g3y;   // g           (h1 = g3x)
    float g2x, g2y;   // A g         (h2 = g2x)
    float g1x, g1y;   // A^2 g       (h3 = g1x)
    float g0x, g0y;   // A^3 g
    float p2x, p2y;   // first row of A^2
    float p3x, p3y;   // first row of A^3
    float m00, m01, m10, m11; // A^4
};

__device__ __forceinline__ C make_coef(const float* __restrict__ b,
                                       const float* __restrict__ a) {
    C c;
    float ia0 = 1.0f / a[0];
    float b0 = b[0] * ia0, b1 = b[1] * ia0, b2 = b[2] * ia0;
    float na1 = -(a[1] * ia0), na2 = -(a[2] * ia0);
    float g0 = fmaf(na1, b0, b1);
    float g1 = fmaf(na2, b0, b2);
    // A = [[na1, 1], [na2, 0]];  A^{k+1} = A^k * A:
    //   (M A)_i0 = M_i0*na1 + M_i1*na2,  (M A)_i1 = M_i0
    float A2_00 = fmaf(na1, na1, na2), A2_01 = na1;
    float A2_10 = na2 * na1,           A2_11 = na2;
    float A3_00 = fmaf(A2_00, na1, A2_01 * na2), A3_01 = A2_00;
    float A3_10 = fmaf(A2_10, na1, A2_11 * na2), A3_11 = A2_10;
    c.m00 = fmaf(A3_00, na1, A3_01 * na2); c.m01 = A3_00;
    c.m10 = fmaf(A3_10, na1, A3_11 * na2); c.m11 = A3_10;
    c.g3x = g0;                          c.g3y = g1;
    c.g2x = fmaf(na1, g0, g1);           c.g2y = na2 * g0;
    c.g1x = fmaf(A2_00, g0, A2_01 * g1); c.g1y = fmaf(A2_10, g0, A2_11 * g1);
    c.g0x = fmaf(A3_00, g0, A3_01 * g1); c.g0y = fmaf(A3_10, g0, A3_11 * g1);
    c.p2x = A2_00; c.p2y = A2_01;
    c.p3x = A3_00; c.p3y = A3_01;
    c.b0 = b0; c.na1 = na1; c.na2 = na2;
    return c;
}

// state-only advance over 4 time-ordered samples (for warm-ups)
__device__ __forceinline__ void warm4(const C& c, float x0, float x1,
                                      float x2, float x3,
                                      float& z0, float& z1) {
    float w0 = fmaf(c.g0x, x0, fmaf(c.g1x, x1, fmaf(c.g2x, x2, c.g3x * x3)));
    float w1 = fmaf(c.g0y, x0, fmaf(c.g1y, x1, fmaf(c.g2y, x2, c.g3y * x3)));
    float nz0 = fmaf(c.m00, z0, fmaf(c.m01, z1, w0));
    float nz1 = fmaf(c.m10, z0, fmaf(c.m11, z1, w1));
    z0 = nz0; z1 = nz1;
}

// full advance with outputs over 4 time-ordered samples
__device__ __forceinline__ void step4(const C& c, float x0, float x1,
                                      float x2, float x3,
                                      float& z0, float& z1,
                                      float& y0, float& y1,
                                      float& y2, float& y3) {
    y0 = fmaf(c.b0, x0, z0);
    y1 = fmaf(c.b0, x1, fmaf(c.g3x, x0, fmaf(c.na1, z0, z1)));
    y2 = fmaf(c.b0, x2, fmaf(c.g3x, x1,
             fmaf(c.g2x, x0, fmaf(c.p2x, z0, c.p2y * z1))));
    y3 = fmaf(c.b0, x3, fmaf(c.g3x, x2, fmaf(c.g2x, x1,
             fmaf(c.g1x, x0, fmaf(c.p3x, z0, c.p3y * z1)))));
    warm4(c, x0, x1, x2, x3, z0, z1);
}

// scalar step
__device__ __forceinline__ void step1(const C& c, float xv,
                                      float& z0, float& z1, float& y) {
    y = fmaf(c.b0, xv, z0);
    float nz0 = fmaf(c.na1, z0, fmaf(c.g3x, xv, z1));
    float nz1 = fmaf(c.na2, z0, c.g3y * xv);
    z0 = nz0; z1 = nz1;
}

__global__ __launch_bounds__(THREADS)
void filtfilt_kernel(const float* __restrict__ x,
                     const float* __restrict__ bc,
                     const float* __restrict__ ac,
                     float* __restrict__ out) {
    extern __shared__ float sm[];

    const int row  = blockIdx.y;
    const int base = blockIdx.x * TILE;
    const int tlen = min(TILE, NE - base);

    const float* xr   = x   + (size_t)row * N;
    float*       outr = out + (size_t)row * N;

    const C c = make_coef(bc, ac);

    // ---- Phase 0: coalesced load of odd-extended x into SMEM ----
    const int len = tlen + 2 * WARM;
    for (int idx = threadIdx.x; idx < len; idx += THREADS) {
        int p = base - WARM + idx;
        float v = 0.0f;
        if (p >= 0 && p < NE) {
            int i = p - PAD;
            if (i < 0)       v = 2.0f * xr[0]     - xr[-i];
            else if (i >= N) v = 2.0f * xr[N - 1] - xr[2 * N - 2 - i];
            else             v = xr[i];
        }
        sm[idx] = v;
    }
    __syncthreads();

    const int s = threadIdx.x * CL;
    const bool active = (s < tlen);
    const int e = active ? min(s + CL, tlen) : s;

    // ---- Phase F1: forward warm-up (48 steps or 0) ----
    float z0 = 0.0f, z1 = 0.0f;
    if (active) {
        int ws = max(0, base + s - WARM) - base;
        for (int t = ws; t + 4 <= s; t += 4) {
            int L = t + WARM;
            warm4(c, sm[L], sm[L + 1], sm[L + 2], sm[L + 3], z0, z1);
        }
    }
    __syncthreads();

    // ---- Phase F2: forward body in-place (+48 tail by last chunk) ----
    if (active) {
        int ebody = e;
        if (e == tlen) ebody = min(e + WARM, NE - base);
        int t = s;
        for (; t + 4 <= ebody; t += 4) {
            int L = t + WARM;
            float y0, y1, y2, y3;
            step4(c, sm[L], sm[L + 1], sm[L + 2], sm[L + 3], z0, z1,
                  y0, y1, y2, y3);
            sm[L] = y0; sm[L + 1] = y1; sm[L + 2] = y2; sm[L + 3] = y3;
        }
        for (; t < ebody; ++t) {
            float y;
            step1(c, sm[t + WARM], z0, z1, y);
            sm[t + WARM] = y;
        }
    }
    __syncthreads();

    // ---- Phase B1: backward warm-up (reads neighbor's y1; regs only) ----
    z0 = 0.0f; z1 = 0.0f;
    if (active) {
        int u = min(e - 1 + WARM, NE - base - 1);   // clamp = exact at seq end
        for (; u - 3 >= e; u -= 4) {
            int L = u + WARM;
            warm4(c, sm[L], sm[L - 1], sm[L - 2], sm[L - 3], z0, z1);
        }
        for (; u >= e; --u) {
            float y;
            step1(c, sm[u + WARM], z0, z1, y);
        }
    }
    __syncthreads();

    // ---- Phase B2: backward body in-place ----
    if (active) {
        int u = e - 1;
        for (; u - 3 >= s; u -= 4) {
            int L = u + WARM;
            float y0, y1, y2, y3;
            step4(c, sm[L], sm[L - 1], sm[L - 2], sm[L - 3], z0, z1,
                  y0, y1, y2, y3);
            sm[L] = y0; sm[L - 1] = y1; sm[L - 2] = y2; sm[L - 3] = y3;
        }
        for (; u >= s; --u) {
            float y;
            step1(c, sm[u + WARM], z0, z1, y);
            sm[u + WARM] = y;
        }
    }
    __syncthreads();

    // ---- Phase 5: coalesced store (crop PAD; reversal implicit) ----
    for (int idx = threadIdx.x; idx < tlen; idx += THREADS) {
        int g = base + idx;
        if (g >= PAD && g < NE - PAD)
            outr[g - PAD] = sm[idx + WARM];
    }
}

extern "C" void kernel_launch(void* const* d_in, const int* in_sizes, int n_in,
                              void* d_out, int out_size) {
    const float* x = (const float*)d_in[0];
    const float* b = (const float*)d_in[1];
    const float* a = (const float*)d_in[2];
    float* out = (float*)d_out;

    cudaFuncSetAttribute(filtfilt_kernel,
                         cudaFuncAttributeMaxDynamicSharedMemorySize,
                         SMEM_BYTES);

    dim3 grid(NTILE, ROWS);
    filtfilt_kernel<<<grid, THREADS, SMEM_BYTES>>>(x, b, a, out);
}

// round 6
// speedup vs baseline: 6.8402x; 2.5562x over previous
#include <cuda_runtime.h>

// Fused filtfilt (order-2 IIR) over 1024 rows x 32768 fp32 samples.
//
// - Reference's max-abs normalization cancels exactly (linear, zero state).
// - Poles |lambda|=0.577 -> 55-step warm-up => ~2e-13 state error; rows split
//   into independent per-thread chunks of CL=45.
// - State-space unroll-by-4: s_{t+4} = A^4 s_t + sum_j A^{3-j} g x_{t+j}.
// - Small tiles (23.5KB smem) -> 9 blocks/SM = 36 warps/SM.
// - WARM+PAD = 64 == 0 mod 4 -> interior blocks load their whole smem window
//   as an aligned float4 stream (full MLP), edges fall back to scalar+mirror.

#define N        32768
#define PAD      9
#define NE       (N + 2 * PAD)        // 32786
#define ROWS     1024
#define WARM     55                   // WARM+PAD = 64 (alignment + accuracy)
#define THREADS  128
#define CL       45                   // odd -> conflict-free smem stride
#define TILE     (CL * THREADS)       // 5760
#define NTILE    6                    // 6*5760 = 34560 >= NE
#define SMEM_FLOATS 5872              // TILE + 2*WARM = 5870, padded to /4
#define SMEM_BYTES  (SMEM_FLOATS * 4) // 23488
#define LEN4     (SMEM_FLOATS / 4)    // 1468

struct C {
    float b0, na1, na2;
    float g3x, g3y;   // g        (h1 = g3x)
    float g2x, g2y;   // A g      (h2 = g2x)
    float g1x, g1y;   // A^2 g    (h3 = g1x)
    float g0x, g0y;   // A^3 g
    float p2x, p2y;   // first row of A^2
    float p3x, p3y;   // first row of A^3
    float m00, m01, m10, m11; // A^4
};

__device__ __forceinline__ C make_coef(const float* __restrict__ b,
                                       const float* __restrict__ a) {
    C c;
    float ia0 = 1.0f / a[0];
    float b0 = b[0] * ia0, b1 = b[1] * ia0, b2 = b[2] * ia0;
    float na1 = -(a[1] * ia0), na2 = -(a[2] * ia0);
    float g0 = fmaf(na1, b0, b1);
    float g1 = fmaf(na2, b0, b2);
    // A = [[na1, 1], [na2, 0]]
    float A2_00 = fmaf(na1, na1, na2), A2_01 = na1;
    float A2_10 = na2 * na1,           A2_11 = na2;
    float A3_00 = fmaf(A2_00, na1, A2_01 * na2), A3_01 = A2_00;
    float A3_10 = fmaf(A2_10, na1, A2_11 * na2), A3_11 = A2_10;
    c.m00 = fmaf(A3_00, na1, A3_01 * na2); c.m01 = A3_00;
    c.m10 = fmaf(A3_10, na1, A3_11 * na2); c.m11 = A3_10;
    c.g3x = g0;                          c.g3y = g1;
    c.g2x = fmaf(na1, g0, g1);           c.g2y = na2 * g0;
    c.g1x = fmaf(A2_00, g0, A2_01 * g1); c.g1y = fmaf(A2_10, g0, A2_11 * g1);
    c.g0x = fmaf(A3_00, g0, A3_01 * g1); c.g0y = fmaf(A3_10, g0, A3_11 * g1);
    c.p2x = A2_00; c.p2y = A2_01;
    c.p3x = A3_00; c.p3y = A3_01;
    c.b0 = b0; c.na1 = na1; c.na2 = na2;
    return c;
}

// state-only advance, 4 time-ordered samples
__device__ __forceinline__ void warm4(const C& c, float x0, float x1,
                                      float x2, float x3,
                                      float& z0, float& z1) {
    float w0 = fmaf(c.g0x, x0, fmaf(c.g1x, x1, fmaf(c.g2x, x2, c.g3x * x3)));
    float w1 = fmaf(c.g0y, x0, fmaf(c.g1y, x1, fmaf(c.g2y, x2, c.g3y * x3)));
    float nz0 = fmaf(c.m00, z0, fmaf(c.m01, z1, w0));
    float nz1 = fmaf(c.m10, z0, fmaf(c.m11, z1, w1));
    z0 = nz0; z1 = nz1;
}

// state-only advance, 1 sample
__device__ __forceinline__ void warm1(const C& c, float xv,
                                      float& z0, float& z1) {
    float nz0 = fmaf(c.na1, z0, fmaf(c.g3x, xv, z1));
    float nz1 = fmaf(c.na2, z0, c.g3y * xv);
    z0 = nz0; z1 = nz1;
}

// full advance with outputs, 4 time-ordered samples
__device__ __forceinline__ void step4(const C& c, float x0, float x1,
                                      float x2, float x3,
                                      float& z0, float& z1,
                                      float& y0, float& y1,
                                      float& y2, float& y3) {
    y0 = fmaf(c.b0, x0, z0);
    y1 = fmaf(c.b0, x1, fmaf(c.g3x, x0, fmaf(c.na1, z0, z1)));
    y2 = fmaf(c.b0, x2, fmaf(c.g3x, x1,
             fmaf(c.g2x, x0, fmaf(c.p2x, z0, c.p2y * z1))));
    y3 = fmaf(c.b0, x3, fmaf(c.g3x, x2, fmaf(c.g2x, x1,
             fmaf(c.g1x, x0, fmaf(c.p3x, z0, c.p3y * z1)))));
    warm4(c, x0, x1, x2, x3, z0, z1);
}

// full advance with output, 1 sample
__device__ __forceinline__ void step1(const C& c, float xv,
                                      float& z0, float& z1, float& y) {
    y = fmaf(c.b0, xv, z0);
    warm1(c, xv, z0, z1);
}

__global__ __launch_bounds__(THREADS)
void filtfilt_kernel(const float* __restrict__ x,
                     const float* __restrict__ bc,
                     const float* __restrict__ ac,
                     float* __restrict__ out) {
    extern __shared__ float sm[];

    const int row  = blockIdx.y;
    const int base = blockIdx.x * TILE;
    const int tlen = min(TILE, NE - base);

    const float* xr   = x   + (size_t)row * N;
    float*       outr = out + (size_t)row * N;

    const C c = make_coef(bc, ac);

    // ---- Phase 0: load smem window = ext positions [base-WARM, base+tlen+WARM)
    // sm[idx] corresponds to x-index  off0 + idx,  off0 = base - (WARM+PAD).
    const int off0 = base - (WARM + PAD);          // multiple of 4 (64)
    if (off0 >= 0 && off0 + SMEM_FLOATS <= N) {
        // fast path: aligned float4 bulk copy (interior blocks)
        const float4* __restrict__ src = (const float4*)(xr + off0);
        float4* dst = (float4*)sm;
        #pragma unroll 4
        for (int i = threadIdx.x; i < LEN4; i += THREADS) dst[i] = src[i];
    } else {
        const int len = tlen + 2 * WARM;
        #pragma unroll 4
        for (int idx = threadIdx.x; idx < len; idx += THREADS) {
            int i = off0 + idx;
            float v;
            if (i < 0)       v = 2.0f * xr[0]     - xr[-i];
            else if (i >= N) v = 2.0f * xr[N - 1] - xr[2 * N - 2 - i];
            else             v = xr[i];
            sm[idx] = v;
        }
    }
    __syncthreads();

    const int s = threadIdx.x * CL;                // rel. to base
    const bool active = (s < tlen);
    const int e = active ? min(s + CL, tlen) : s;

    // ---- Phase F1: forward warm-up (state only) ----
    float z0 = 0.0f, z1 = 0.0f;
    if (active) {
        int t = max(0, base + s - WARM) - base;
        for (; t + 4 <= s; t += 4) {
            int L = t + WARM;
            warm4(c, sm[L], sm[L + 1], sm[L + 2], sm[L + 3], z0, z1);
        }
        for (; t < s; ++t) warm1(c, sm[t + WARM], z0, z1);
    }
    __syncthreads();

    // ---- Phase F2: forward body in-place (+WARM tail by last chunk) ----
    if (active) {
        int ebody = e;
        if (e == tlen) ebody = min(e + WARM, NE - base);
        int t = s;
        for (; t + 4 <= ebody; t += 4) {
            int L = t + WARM;
            float y0, y1, y2, y3;
            step4(c, sm[L], sm[L + 1], sm[L + 2], sm[L + 3], z0, z1,
                  y0, y1, y2, y3);
            sm[L] = y0; sm[L + 1] = y1; sm[L + 2] = y2; sm[L + 3] = y3;
        }
        for (; t < ebody; ++t) {
            float y;
            step1(c, sm[t + WARM], z0, z1, y);
            sm[t + WARM] = y;
        }
    }
    __syncthreads();

    // ---- Phase B1: backward warm-up (reads neighbor's y1; state only) ----
    z0 = 0.0f; z1 = 0.0f;
    if (active) {
        int u = min(e - 1 + WARM, NE - base - 1);  // clamp = exact at seq end
        for (; u - 3 >= e; u -= 4) {
            int L = u + WARM;
            warm4(c, sm[L], sm[L - 1], sm[L - 2], sm[L - 3], z0, z1);
        }
        for (; u >= e; --u) warm1(c, sm[u + WARM], z0, z1);
    }
    __syncthreads();

    // ---- Phase B2: backward body in-place ----
    if (active) {
        int u = e - 1;
        for (; u - 3 >= s; u -= 4) {
            int L = u + WARM;
            float y0, y1, y2, y3;
            step4(c, sm[L], sm[L - 1], sm[L - 2], sm[L - 3], z0, z1,
                  y0, y1, y2, y3);
            sm[L] = y0; sm[L - 1] = y1; sm[L - 2] = y2; sm[L - 3] = y3;
        }
        for (; u >= s; --u) {
            float y;
            step1(c, sm[u + WARM], z0, z1, y);
            sm[u + WARM] = y;
        }
    }
    __syncthreads();

    // ---- Phase 5: coalesced store (crop PAD; reversal implicit) ----
    #pragma unroll 4
    for (int idx = threadIdx.x; idx < tlen; idx += THREADS) {
        int g = base + idx;
        if (g >= PAD && g < NE - PAD)
            outr[g - PAD] = sm[idx + WARM];
    }
}

extern "C" void kernel_launch(void* const* d_in, const int* in_sizes, int n_in,
                              void* d_out, int out_size) {
    const float* x = (const float*)d_in[0];
    const float* b = (const float*)d_in[1];
    const float* a = (const float*)d_in[2];
    float* out = (float*)d_out;

    dim3 grid(NTILE, ROWS);
    filtfilt_kernel<<<grid, THREADS, SMEM_BYTES>>>(x, b, a, out);
}

// round 7
// speedup vs baseline: 7.2657x; 1.0622x over previous
#include <cuda_runtime.h>

// Fused filtfilt (order-2 IIR) over 1024 rows x 32768 fp32 samples.
//
// - Reference's max-abs normalization cancels exactly (linear, zero state).
// - Poles |lambda|=0.577 -> 32-step warm-up => ~2.3e-8 state error.
// - State-space unroll-by-4: s_{t+4} = A^4 s_t + sum_j A^{3-j} g x_{t+j}.
// - Alignment scheme: chunk starts s = tid*CL + 1 (CL=44, mult of 4) and
//   smem window mapped at off0 = base-40 (mult of 4, since PAD=9) make every
//   smem access in warm/body/store phases a 16B-aligned float4 -> LDS.128 /
//   STS.128 everywhere, conflict-free (lane stride 44 floats).

#define N        32768
#define PAD      9
#define NE       (N + 2 * PAD)        // 32786
#define ROWS     1024
#define WARM     32
#define THREADS  128
#define CL       44
#define TILE     (CL * THREADS)       // 5632
#define NTILE    6                    // 6*5632 = 33792 >= NE
#define SMEM_FLOATS (TILE + 2 * WARM) // 5696 (covers m <= tlen+62)
#define SMEM_BYTES  (SMEM_FLOATS * 4) // 22784

// smem index m <-> x-index off0 + m, off0 = base - 40
//               <-> ext position t = m - 31 + base  (m = t + 31, t tile-rel)

struct C {
    float b0, na1, na2;
    float g3x, g3y;   // g        (h1)
    float g2x, g2y;   // A g      (h2)
    float g1x, g1y;   // A^2 g    (h3)
    float g0x, g0y;   // A^3 g
    float p2x, p2y;   // first row of A^2
    float p3x, p3y;   // first row of A^3
    float m00, m01, m10, m11; // A^4
};

__device__ __forceinline__ C make_coef(const float* __restrict__ b,
                                       const float* __restrict__ a) {
    C c;
    float ia0 = 1.0f / a[0];
    float b0 = b[0] * ia0, b1 = b[1] * ia0, b2 = b[2] * ia0;
    float na1 = -(a[1] * ia0), na2 = -(a[2] * ia0);
    float g0 = fmaf(na1, b0, b1);
    float g1 = fmaf(na2, b0, b2);
    float A2_00 = fmaf(na1, na1, na2), A2_01 = na1;
    float A2_10 = na2 * na1,           A2_11 = na2;
    float A3_00 = fmaf(A2_00, na1, A2_01 * na2), A3_01 = A2_00;
    float A3_10 = fmaf(A2_10, na1, A2_11 * na2), A3_11 = A2_10;
    c.m00 = fmaf(A3_00, na1, A3_01 * na2); c.m01 = A3_00;
    c.m10 = fmaf(A3_10, na1, A3_11 * na2); c.m11 = A3_10;
    c.g3x = g0;                          c.g3y = g1;
    c.g2x = fmaf(na1, g0, g1);           c.g2y = na2 * g0;
    c.g1x = fmaf(A2_00, g0, A2_01 * g1); c.g1y = fmaf(A2_10, g0, A2_11 * g1);
    c.g0x = fmaf(A3_00, g0, A3_01 * g1); c.g0y = fmaf(A3_10, g0, A3_11 * g1);
    c.p2x = A2_00; c.p2y = A2_01;
    c.p3x = A3_00; c.p3y = A3_01;
    c.b0 = b0; c.na1 = na1; c.na2 = na2;
    return c;
}

// x0 = earliest sample in filter time
__device__ __forceinline__ void warm4(const C& c, float x0, float x1,
                                      float x2, float x3,
                                      float& z0, float& z1) {
    float w0 = fmaf(c.g0x, x0, fmaf(c.g1x, x1, fmaf(c.g2x, x2, c.g3x * x3)));
    float w1 = fmaf(c.g0y, x0, fmaf(c.g1y, x1, fmaf(c.g2y, x2, c.g3y * x3)));
    float nz0 = fmaf(c.m00, z0, fmaf(c.m01, z1, w0));
    float nz1 = fmaf(c.m10, z0, fmaf(c.m11, z1, w1));
    z0 = nz0; z1 = nz1;
}

__device__ __forceinline__ void warm1(const C& c, float xv,
                                      float& z0, float& z1) {
    float nz0 = fmaf(c.na1, z0, fmaf(c.g3x, xv, z1));
    float nz1 = fmaf(c.na2, z0, c.g3y * xv);
    z0 = nz0; z1 = nz1;
}

__device__ __forceinline__ void step4(const C& c, float x0, float x1,
                                      float x2, float x3,
                                      float& z0, float& z1,
                                      float& y0, float& y1,
                                      float& y2, float& y3) {
    y0 = fmaf(c.b0, x0, z0);
    y1 = fmaf(c.b0, x1, fmaf(c.g3x, x0, fmaf(c.na1, z0, z1)));
    y2 = fmaf(c.b0, x2, fmaf(c.g3x, x1,
             fmaf(c.g2x, x0, fmaf(c.p2x, z0, c.p2y * z1))));
    y3 = fmaf(c.b0, x3, fmaf(c.g3x, x2, fmaf(c.g2x, x1,
             fmaf(c.g1x, x0, fmaf(c.p3x, z0, c.p3y * z1)))));
    warm4(c, x0, x1, x2, x3, z0, z1);
}

__device__ __forceinline__ void step1(const C& c, float xv,
                                      float& z0, float& z1, float& y) {
    y = fmaf(c.b0, xv, z0);
    warm1(c, xv, z0, z1);
}

__global__ __launch_bounds__(THREADS)
void filtfilt_kernel(const float* __restrict__ x,
                     const float* __restrict__ bc,
                     const float* __restrict__ ac,
                     float* __restrict__ out) {
    extern __shared__ float sm[];
    float4* sm4 = (float4*)sm;

    const int tid  = threadIdx.x;
    const int row  = blockIdx.y;
    const int base = blockIdx.x * TILE;
    const int tlen = min(TILE, NE - base);
    const int off0 = base - (WARM + PAD - 1);      // base - 40, mult of 4

    const float* xr   = x   + (size_t)row * N;
    float*       outr = out + (size_t)row * N;

    const C c = make_coef(bc, ac);

    // ---- Phase 0: load window sm[m] = x[off0 + m] ----
    if (off0 >= 0 && off0 + SMEM_FLOATS <= N) {
        const float4* __restrict__ src = (const float4*)(xr + off0);
        #pragma unroll 4
        for (int i = tid; i < SMEM_FLOATS / 4; i += THREADS)
            sm4[i] = src[i];
    } else {
        #pragma unroll 4
        for (int idx = tid; idx < SMEM_FLOATS; idx += THREADS) {
            int i = off0 + idx;
            float v;
            if (i < 0)       v = 2.0f * xr[0]     - xr[-i];
            else if (i >= N) v = 2.0f * xr[N - 1] - xr[2 * N - 2 - i];
            else             v = xr[i];
            sm[idx] = v;
        }
    }
    __syncthreads();

    // chunk [sbeg, e) in tile-relative ext coords; m(t) = t + 31
    const int s    = tid * CL + 1;
    const int sbeg = (tid == 0) ? 0 : s;
    const bool active = (sbeg < tlen);
    const int e = active ? min(s + CL, tlen) : sbeg;

    // ---- Phase F1: forward warm-up (state only, reads x) ----
    float z0 = 0.0f, z1 = 0.0f;
    if (active) {
        if (tid == 0) {
            if (base > 0) {                          // 31 scalar steps, m in [0,31)
                #pragma unroll 4
                for (int m = 0; m < WARM - 1; ++m) warm1(c, sm[m], z0, z1);
            }                                        // base==0: exact zero state
        } else {
            const float4* p4 = sm4 + ((s - 1) >> 2); // m = s-1, aligned
            #pragma unroll
            for (int g = 0; g < WARM / 4; ++g) {
                float4 f = p4[g];
                warm4(c, f.x, f.y, f.z, f.w, z0, z1);
            }
        }
    }
    __syncthreads();

    // ---- Phase F2: forward body in-place (+WARM tail by last active) ----
    if (active) {
        int ebody = e;
        if (e == tlen) ebody = min(e + WARM, NE - base);
        int t = sbeg;
        while (t < ebody && ((t + 31) & 3) != 0) {   // <=1 iter (tid 0 only)
            float y; step1(c, sm[t + 31], z0, z1, y); sm[t + 31] = y; ++t;
        }
        for (; t + 4 <= ebody; t += 4) {
            int mi = (t + 31) >> 2;
            float4 f = sm4[mi];
            float y0, y1, y2, y3;
            step4(c, f.x, f.y, f.z, f.w, z0, z1, y0, y1, y2, y3);
            sm4[mi] = make_float4(y0, y1, y2, y3);
        }
        for (; t < ebody; ++t) {
            float y; step1(c, sm[t + 31], z0, z1, y); sm[t + 31] = y;
        }
    }
    __syncthreads();

    // ---- Phase B1: backward warm-up (reads next chunk's y1; state only) ----
    z0 = 0.0f; z1 = 0.0f;
    if (active) {
        int u = min(e + WARM - 1, NE - base - 1);    // clamp = exact at seq end
        while (u >= e && ((u + 31) & 3) != 3) { warm1(c, sm[u + 31], z0, z1); --u; }
        for (; u - 3 >= e; u -= 4) {
            float4 f = sm4[(u + 28) >> 2];
            warm4(c, f.w, f.z, f.y, f.x, z0, z1);    // descending time
        }
        for (; u >= e; --u) warm1(c, sm[u + 31], z0, z1);
    }
    __syncthreads();

    // ---- Phase B2: backward body in-place ----
    if (active) {
        int u = e - 1;
        while (u >= sbeg && ((u + 31) & 3) != 3) {
            float y; step1(c, sm[u + 31], z0, z1, y); sm[u + 31] = y; --u;
        }
        for (; u - 3 >= sbeg; u -= 4) {
            int mi = (u + 28) >> 2;
            float4 f = sm4[mi];
            float y0, y1, y2, y3;
            step4(c, f.w, f.z, f.y, f.x, z0, z1, y0, y1, y2, y3);
            sm4[mi] = make_float4(y3, y2, y1, y0);
        }
        for (; u >= sbeg; --u) {
            float y; step1(c, sm[u + 31], z0, z1, y); sm[u + 31] = y;
        }
    }
    __syncthreads();

    // ---- Phase 5: store sm[m] -> outr[off0 + m] (crop falls out of clips) ----
    {
        int M0 = max(31, -off0);                     // o >= 0
        int M1 = min(31 + tlen, N - off0);           // o < N
        int mA = (M0 + 3) & ~3;
        int mB = M1 & ~3;
        if (tid < mA - M0) { int m = M0 + tid; outr[off0 + m] = sm[m]; }
        if (tid < M1 - mB) { int m = mB + tid; outr[off0 + m] = sm[m]; }
        float4* dst4 = (float4*)(outr + off0);       // off0 mult of 4
        #pragma unroll 4
        for (int mi = (mA >> 2) + tid; mi < (mB >> 2); mi += THREADS)
            dst4[mi] = sm4[mi];
    }
}

extern "C" void kernel_launch(void* const* d_in, const int* in_sizes, int n_in,
                              void* d_out, int out_size) {
    const float* x = (const float*)d_in[0];
    const float* b = (const float*)d_in[1];
    const float* a = (const float*)d_in[2];
    float* out = (float*)d_out;

    dim3 grid(NTILE, ROWS);
    filtfilt_kernel<<<grid, THREADS, SMEM_BYTES>>>(x, b, a, out);
}